// round 6
// baseline (speedup 1.0000x reference)
#include <cuda_runtime.h>

// MultiHeadAttention: B=4096, T=128, C=128, H=4, D=32, causal, scale = C^-0.5
// One CTA per batch element, fp32 with packed f32x2 FMA (FFMA2).
// R5: 512 threads/CTA (4 warps/SMSP) for latency hiding; per-thread tiles halved;
//     SCALE folded into Q store.

#define NB 4096
#define TT 128
#define CC 128
#define HH 4
#define DD 32
#define SCALE 0.08838834764831845f   // 1/sqrt(128)

// shared memory layout (float offsets)
#define OFF_XST 0         // xst[c][t]   [128][132]
#define OFF_QT  16896     // qt[d][t]    [32][132]  (pre-scaled by SCALE)
#define OFF_KT  21120     // kt[d][s]    [32][132]
#define OFF_VV  25344     // vv[s][d]    [128][36]
#define OFF_WUN 29952     // union: w3[3][128][36] (13824) / pt[s][t] [128][132] (16896)
#define OFF_OT  46848     // ot[d][t]    [32][132]
#define OFF_WPT 51072     // wpt[d][c]   [32][132]
#define OFF_BPS 55296     // bps[128]
#define SMEM_FLOATS 55424

typedef unsigned long long u64t;

__device__ __forceinline__ u64t fma2(u64t a, u64t b, u64t c) {
    u64t d;
    asm("fma.rn.f32x2 %0, %1, %2, %3;" : "=l"(d) : "l"(a), "l"(b), "l"(c));
    return d;
}
__device__ __forceinline__ u64t splat2(float x) {
    u64t r;
    asm("mov.b64 %0, {%1, %2};" : "=l"(r) : "f"(x), "f"(x));
    return r;
}
__device__ __forceinline__ float2 unpack2(u64t v) {
    float2 r;
    asm("mov.b64 {%0, %1}, %2;" : "=f"(r.x), "=f"(r.y) : "l"(v));
    return r;
}

__global__ void __launch_bounds__(512, 1)
mha_f32x2_kernel(const float* __restrict__ x,
                 const float* __restrict__ Wq,
                 const float* __restrict__ Wk,
                 const float* __restrict__ Wv,
                 const float* __restrict__ Wp,
                 const float* __restrict__ bp,
                 float* __restrict__ out)
{
    extern __shared__ float sm[];
    float* xst = sm + OFF_XST;
    float* qt  = sm + OFF_QT;
    float* kt  = sm + OFF_KT;
    float* vv  = sm + OFF_VV;
    float* wun = sm + OFF_WUN;   // W staging, later P (transposed+swizzled)
    float* ot  = sm + OFF_OT;
    float* wpt = sm + OFF_WPT;
    float* bps = sm + OFF_BPS;

    const int tid = threadIdx.x;
    const int b   = blockIdx.x;
    const float* xb = x + (size_t)b * (TT * CC);

    // ---- load x transposed: xst[c][t] = x[t][c] ----
    {
        int t  = tid >> 2;
        int ch = (tid & 3) * 32;
        #pragma unroll
        for (int j = 0; j < 8; ++j) {
            int c = ch + j * 4;
            float4 v = *reinterpret_cast<const float4*>(xb + t * CC + c);
            xst[(c + 0) * 132 + t] = v.x;
            xst[(c + 1) * 132 + t] = v.y;
            xst[(c + 2) * 132 + t] = v.z;
            xst[(c + 3) * 132 + t] = v.w;
        }
        if (tid < 128) bps[tid] = bp[tid];
    }

    // thread tilings (512 threads)
    const int g16 = tid & 15;        // 0..15
    const int g32 = tid >> 4;        // 0..31
    const int r0  = g32 * 4;         // row group (G1/G3): 4 rows
    const int d0  = g16 * 2;         // col group (G1/G3): 2 cols (1 u64)
    const int sr0 = g32 * 4;         // G2 score rows (4)
    const int ss0 = g16 * 8;         // G2 score cols (8)
    const int t0  = g32 * 4;         // G4/out rows
    const int c0  = g16 * 8;         // G4/out cols

    // persistent output accumulator: 4 rows x 8 cols of out[T][C]
    u64t oacc[4][4];
    #pragma unroll
    for (int i = 0; i < 4; ++i)
        #pragma unroll
        for (int j = 0; j < 4; ++j) oacc[i][j] = 0ull;

    for (int h = 0; h < HH; ++h) {
        __syncthreads();   // protects wun/wpt reuse across head iterations

        // ---- stage W for this head ----
        {
            #pragma unroll
            for (int m = 0; m < 3; ++m) {
                const float* wsrc = (m == 0) ? (Wq + h * CC * DD)
                                  : (m == 1) ? (Wk + h * CC * DD)
                                             : (Wv + h * CC * DD);
                float* wdst = wun + m * 4608;     // [128][36]
                #pragma unroll
                for (int f = 0; f < CC * DD; f += 2048) {
                    int ff = f + tid * 4;
                    int k = ff >> 5, d = ff & 31;
                    float4 v = *reinterpret_cast<const float4*>(wsrc + ff);
                    *reinterpret_cast<float4*>(wdst + k * 36 + d) = v;
                }
            }
            // wpt[d][c] = Wp[c][h*32+d]
            int c  = tid >> 2;
            int dh = (tid & 3) * 8;
            #pragma unroll
            for (int j = 0; j < 8; j += 4) {
                float4 v = *reinterpret_cast<const float4*>(Wp + c * CC + h * DD + dh + j);
                wpt[(dh + j + 0) * 132 + c] = v.x;
                wpt[(dh + j + 1) * 132 + c] = v.y;
                wpt[(dh + j + 2) * 132 + c] = v.z;
                wpt[(dh + j + 3) * 132 + c] = v.w;
            }
        }
        __syncthreads();

        // ---- G1 (fused): Q,K,V = x @ {Wq,Wk,Wv} ; 4 rows x 2 cols per thread ----
        {
            u64t acc[3][4];
            #pragma unroll
            for (int m = 0; m < 3; ++m)
                #pragma unroll
                for (int i = 0; i < 4; ++i) acc[m][i] = 0ull;

            #pragma unroll 4
            for (int k = 0; k < CC; ++k) {
                float4 a = *reinterpret_cast<const float4*>(xst + k * 132 + r0);
                u64t a0 = splat2(a.x), a1 = splat2(a.y), a2 = splat2(a.z), a3 = splat2(a.w);
                #pragma unroll
                for (int m = 0; m < 3; ++m) {
                    u64t bb = *reinterpret_cast<const u64t*>(wun + m * 4608 + k * 36 + d0);
                    acc[m][0] = fma2(a0, bb, acc[m][0]);
                    acc[m][1] = fma2(a1, bb, acc[m][1]);
                    acc[m][2] = fma2(a2, bb, acc[m][2]);
                    acc[m][3] = fma2(a3, bb, acc[m][3]);
                }
            }
            // epilogues: Q (pre-scaled), K transposed; V natural (u64 stores)
            #pragma unroll
            for (int i = 0; i < 4; ++i) {
                float2 vq = unpack2(acc[0][i]);
                qt[(d0 + 0) * 132 + r0 + i] = vq.x * SCALE;
                qt[(d0 + 1) * 132 + r0 + i] = vq.y * SCALE;
                float2 vk = unpack2(acc[1][i]);
                kt[(d0 + 0) * 132 + r0 + i] = vk.x;
                kt[(d0 + 1) * 132 + r0 + i] = vk.y;
                *reinterpret_cast<u64t*>(vv + (r0 + i) * 36 + d0) = acc[2][i];
            }
        }
        __syncthreads();

        // ---- G2: S = Q K^T, causal softmax -> pt (4x8 tiles, k=32) ----
        {
            const bool live = (2 * g16 <= g32);   // tile touches the causal triangle

            float p[4][8];
            if (live) {
                u64t sacc[4][4];
                #pragma unroll
                for (int i = 0; i < 4; ++i)
                    #pragma unroll
                    for (int j = 0; j < 4; ++j) sacc[i][j] = 0ull;

                #pragma unroll 4
                for (int d = 0; d < DD; ++d) {
                    const float* qrow = qt + d * 132;
                    const float* krow = kt + d * 132;
                    float4 a = *reinterpret_cast<const float4*>(qrow + sr0);
                    const u64t* kb = reinterpret_cast<const u64t*>(krow + ss0);
                    u64t b0 = kb[0], b1 = kb[1], b2 = kb[2], b3 = kb[3];
                    float ar[4] = {a.x, a.y, a.z, a.w};
                    #pragma unroll
                    for (int i = 0; i < 4; ++i) {
                        u64t ap = splat2(ar[i]);
                        sacc[i][0] = fma2(ap, b0, sacc[i][0]);
                        sacc[i][1] = fma2(ap, b1, sacc[i][1]);
                        sacc[i][2] = fma2(ap, b2, sacc[i][2]);
                        sacc[i][3] = fma2(ap, b3, sacc[i][3]);
                    }
                }
                #pragma unroll
                for (int i = 0; i < 4; ++i) {
                    int r = sr0 + i;
                    #pragma unroll
                    for (int jp = 0; jp < 4; ++jp) {
                        float2 v = unpack2(sacc[i][jp]);
                        int s = ss0 + 2 * jp;
                        p[i][2 * jp]     = (s     <= r) ? v.x : -3.0e38f;
                        p[i][2 * jp + 1] = (s + 1 <= r) ? v.y : -3.0e38f;
                    }
                }
            } else {
                #pragma unroll
                for (int i = 0; i < 4; ++i)
                    #pragma unroll
                    for (int j = 0; j < 8; ++j) p[i][j] = -3.0e38f;
            }

            // row softmax: reduce across the 16 g16 lanes (lane bits 0..3)
            #pragma unroll
            for (int i = 0; i < 4; ++i) {
                float m = p[i][0];
                #pragma unroll
                for (int j = 1; j < 8; ++j) m = fmaxf(m, p[i][j]);
                #pragma unroll
                for (int o = 1; o < 16; o <<= 1)
                    m = fmaxf(m, __shfl_xor_sync(0xffffffffu, m, o));
                float sum = 0.f;
                #pragma unroll
                for (int j = 0; j < 8; ++j) { float e = __expf(p[i][j] - m); p[i][j] = e; sum += e; }
                #pragma unroll
                for (int o = 1; o < 16; o <<= 1)
                    sum += __shfl_xor_sync(0xffffffffu, sum, o);
                float inv = __frcp_rn(sum);
                #pragma unroll
                for (int j = 0; j < 8; ++j) p[i][j] *= inv;
            }

            // store pt[s][r] with XOR swizzle on r bits 2..4
            // skipped tiles (dead) are provably never read by G3 (it reads only s<=t)
            if (live) {
                #pragma unroll
                for (int j = 0; j < 8; ++j) {
                    int s  = ss0 + j;
                    int xr = ((s >> 3) & 7) << 2;
                    float* prow = wun + s * 132;
                    int rb = sr0 ^ xr;           // sr0 is 4-aligned; xr has bits 2..4
                    #pragma unroll
                    for (int i = 0; i < 4; ++i)
                        prow[rb + i] = p[i][j];
                }
            }
        }
        __syncthreads();

        // ---- G3: O = P @ V  (4 rows x 2 cols, causal bound: P[t][s]=0 for s>t) ----
        {
            u64t acc[4];
            #pragma unroll
            for (int i = 0; i < 4; ++i) acc[i] = 0ull;
            const int send = r0 + 4;   // rows r0..r0+3 only need s <= r0+3
            #pragma unroll 4
            for (int s = 0; s < send; ++s) {
                int xr = ((s >> 3) & 7) << 2;
                const float* prow = wun + s * 132;
                float4 a = *reinterpret_cast<const float4*>(prow + (r0 ^ xr));
                u64t bb = *reinterpret_cast<const u64t*>(vv + s * 36 + d0);
                acc[0] = fma2(splat2(a.x), bb, acc[0]);
                acc[1] = fma2(splat2(a.y), bb, acc[1]);
                acc[2] = fma2(splat2(a.z), bb, acc[2]);
                acc[3] = fma2(splat2(a.w), bb, acc[3]);
            }
            // store transposed: ot[d][t]
            #pragma unroll
            for (int i = 0; i < 4; ++i) {
                float2 v = unpack2(acc[i]);
                ot[(d0 + 0) * 132 + r0 + i] = v.x;
                ot[(d0 + 1) * 132 + r0 + i] = v.y;
            }
        }
        __syncthreads();

        // ---- G4: out_acc += O @ Wp_h^T  (4x8 tiles, k=32, register-resident) ----
        {
            #pragma unroll 4
            for (int d = 0; d < DD; ++d) {
                const float* orow = ot + d * 132;
                const float* wrow = wpt + d * 132;
                float4 a = *reinterpret_cast<const float4*>(orow + t0);
                const u64t* wb = reinterpret_cast<const u64t*>(wrow + c0);
                u64t b0 = wb[0], b1 = wb[1], b2 = wb[2], b3 = wb[3];
                float ar[4] = {a.x, a.y, a.z, a.w};
                #pragma unroll
                for (int i = 0; i < 4; ++i) {
                    u64t ap = splat2(ar[i]);
                    oacc[i][0] = fma2(ap, b0, oacc[i][0]);
                    oacc[i][1] = fma2(ap, b1, oacc[i][1]);
                    oacc[i][2] = fma2(ap, b2, oacc[i][2]);
                    oacc[i][3] = fma2(ap, b3, oacc[i][3]);
                }
            }
        }
    }

    // ---- epilogue: out = acc + bp ----
    {
        float bv[8];
        #pragma unroll
        for (int j = 0; j < 8; ++j) bv[j] = bps[c0 + j];
        #pragma unroll
        for (int i = 0; i < 4; ++i) {
            float2 p0 = unpack2(oacc[i][0]);
            float2 p1 = unpack2(oacc[i][1]);
            float2 p2 = unpack2(oacc[i][2]);
            float2 p3 = unpack2(oacc[i][3]);
            float4 v0 = make_float4(p0.x + bv[0], p0.y + bv[1], p1.x + bv[2], p1.y + bv[3]);
            float4 v1 = make_float4(p2.x + bv[4], p2.y + bv[5], p3.x + bv[6], p3.y + bv[7]);
            size_t base = ((size_t)b * TT + (t0 + i)) * CC + c0;
            *reinterpret_cast<float4*>(out + base)     = v0;
            *reinterpret_cast<float4*>(out + base + 4) = v1;
        }
    }
}

extern "C" void kernel_launch(void* const* d_in, const int* in_sizes, int n_in,
                              void* d_out, int out_size)
{
    (void)in_sizes; (void)n_in; (void)out_size;
    const float* x  = (const float*)d_in[0];
    const float* Wq = (const float*)d_in[1];
    const float* Wk = (const float*)d_in[2];
    const float* Wv = (const float*)d_in[3];
    const float* Wp = (const float*)d_in[4];
    const float* bp = (const float*)d_in[5];
    float* out = (float*)d_out;

    const int smem_bytes = SMEM_FLOATS * 4;   // 221,696 B
    cudaFuncSetAttribute(mha_f32x2_kernel,
                         cudaFuncAttributeMaxDynamicSharedMemorySize, smem_bytes);
    mha_f32x2_kernel<<<NB, 512, smem_bytes>>>(x, Wq, Wk, Wv, Wp, bp, out);
}

// round 11
// speedup vs baseline: 1.4823x; 1.4823x over previous
#include <cuda_runtime.h>
#include <cuda_bf16.h>
#include <cstdint>

// MHA B=4096,T=128,C=128,H=4,D=32 causal, scale=C^-0.5
// Warp-level mma.sync (bf16, fp32 accum) with hi/lo split precision.
// 1 CTA per batch, 512 threads = 16 warps (4x4 warp grid).

#define NB 4096
#define SCALE 0.08838834764831845f

// smem row strides (bytes): i*stride mod 128 = 16*i -> conflict-free ldmatrix
#define S128 272   // K=128 bf16 rows (256B) + 16 pad
#define S32  80    // K=32  bf16 rows (64B)  + 16 pad

// smem byte offsets
#define O_XH   0                  // x hi  [128][128] bf16
#define O_XL   34816              // x lo
#define O_PH   69632              // P hi [128][128]   (union with WH)
#define O_PL   104448             // P lo              (union with WL)
#define O_WH   69632              // W^T hi [96][128]  (n = m*32+d, k = c)
#define O_WL   104448
#define O_QT   139264             // Q bf16 [128][32] (pre-scaled)
#define O_KT   149504             // K bf16 [128][32]
#define O_VTH  159744             // V^T hi [32][128]  (d rows, s cols)
#define O_VTL  168448
#define O_OH   177152             // O hi [128][32]
#define O_OL   187392
#define O_WPH  197632             // Wp hi [128 c][32 d]
#define O_WPL  207872
#define O_RED  218112             // float [4 wc][2][128] softmax partials
#define SMEM_BYTES 222208

__device__ __forceinline__ uint32_t cvta_s(const void* p) {
    uint32_t a;
    asm("{ .reg .u64 t; cvta.to.shared.u64 t, %1; cvt.u32.u64 %0, t; }" : "=r"(a) : "l"(p));
    return a;
}
__device__ __forceinline__ void ldsm4(uint32_t* r, uint32_t a) {
    asm volatile("ldmatrix.sync.aligned.m8n8.x4.shared.b16 {%0,%1,%2,%3}, [%4];"
                 : "=r"(r[0]), "=r"(r[1]), "=r"(r[2]), "=r"(r[3]) : "r"(a));
}
__device__ __forceinline__ void ldsm2(uint32_t* r, uint32_t a) {
    asm volatile("ldmatrix.sync.aligned.m8n8.x2.shared.b16 {%0,%1}, [%2];"
                 : "=r"(r[0]), "=r"(r[1]) : "r"(a));
}
__device__ __forceinline__ void mma16816(float* c, const uint32_t* a, const uint32_t* b) {
    asm volatile("mma.sync.aligned.m16n8k16.row.col.f32.bf16.bf16.f32 "
                 "{%0,%1,%2,%3}, {%4,%5,%6,%7}, {%8,%9}, {%0,%1,%2,%3};"
                 : "+f"(c[0]), "+f"(c[1]), "+f"(c[2]), "+f"(c[3])
                 : "r"(a[0]), "r"(a[1]), "r"(a[2]), "r"(a[3]), "r"(b[0]), "r"(b[1]));
}
// pack two floats as bf16x2: lo -> lower half, hi -> upper half
__device__ __forceinline__ uint32_t packbf(float lo, float hi) {
    uint32_t d;
    asm("cvt.rn.bf16x2.f32 %0, %1, %2;" : "=r"(d) : "f"(hi), "f"(lo));
    return d;
}
__device__ __forceinline__ void split2(float v, float& h, float& l) {
    __nv_bfloat16 hb = __float2bfloat16(v);
    h = __bfloat162float(hb);
    l = v - h;
}

__global__ void __launch_bounds__(512, 1)
mha_mma_kernel(const float* __restrict__ x,
               const float* __restrict__ Wq,
               const float* __restrict__ Wk,
               const float* __restrict__ Wv,
               const float* __restrict__ Wp,
               const float* __restrict__ bp,
               float* __restrict__ out)
{
    extern __shared__ char sm[];
    const uint32_t sb = cvta_s(sm);
    const int tid  = threadIdx.x;
    const int lane = tid & 31;
    const int warp = tid >> 5;
    const int wr   = warp >> 2;      // warp row group (m0 = wr*32)
    const int wc   = warp & 3;       // warp col group
    const int g    = lane >> 2;      // fragment row within 8
    const int qj   = lane & 3;       // fragment col quad
    const int b    = blockIdx.x;

    // ---- stage x -> XH/XL (bf16 hi/lo, K-major rows t) ----
    {
        int t = tid >> 2, cb = (tid & 3) * 32;
        const float* xr = x + ((size_t)b * 128 + t) * 128 + cb;
        uint32_t base = (uint32_t)t * S128 + cb * 2;
        #pragma unroll
        for (int i = 0; i < 32; i += 2) {
            float2 v = *reinterpret_cast<const float2*>(xr + i);
            float h0, l0, h1, l1;
            split2(v.x, h0, l0); split2(v.y, h1, l1);
            *reinterpret_cast<uint32_t*>(sm + O_XH + base + i * 2) = packbf(h0, h1);
            *reinterpret_cast<uint32_t*>(sm + O_XL + base + i * 2) = packbf(l0, l1);
        }
    }

    float oacc[8][4];   // persistent out fragments (2 mt x 4 nt)
    #pragma unroll
    for (int f = 0; f < 8; ++f)
        #pragma unroll
        for (int r = 0; r < 4; ++r) oacc[f][r] = 0.f;

    for (int h = 0; h < 4; ++h) {
        // ---- stage W^T (Wq|Wk|Wv rows n=m*32+d, k=c) and Wp slice ----
        {
            int c = tid >> 2, db = (tid & 3) * 8;
            #pragma unroll
            for (int m = 0; m < 3; ++m) {
                const float* w = ((m == 0) ? Wq : (m == 1) ? Wk : Wv)
                                 + ((size_t)h * 128 + c) * 32 + db;
                #pragma unroll
                for (int i = 0; i < 8; ++i) {
                    float hv, lv;
                    split2(w[i], hv, lv);
                    int n = m * 32 + db + i;
                    *reinterpret_cast<__nv_bfloat16*>(sm + O_WH + n * S128 + c * 2) = __float2bfloat16(hv);
                    *reinterpret_cast<__nv_bfloat16*>(sm + O_WL + n * S128 + c * 2) = __float2bfloat16(lv);
                }
            }
            const float* wp = Wp + (size_t)c * 128 + h * 32 + db;
            #pragma unroll
            for (int i = 0; i < 8; i += 2) {
                float h0, l0, h1, l1;
                split2(wp[i], h0, l0); split2(wp[i + 1], h1, l1);
                *reinterpret_cast<uint32_t*>(sm + O_WPH + c * S32 + (db + i) * 2) = packbf(h0, h1);
                *reinterpret_cast<uint32_t*>(sm + O_WPL + c * S32 + (db + i) * 2) = packbf(l0, l1);
            }
        }
        __syncthreads();

        // ---- G1: QKV[t][n] = sum_c x[t][c]*W^T[n][c]  M128 N96 K128, split 3-pass ----
        {
            const int m0 = wr * 32, n0 = wc * 24;
            float acc[6][4];
            #pragma unroll
            for (int f = 0; f < 6; ++f)
                #pragma unroll
                for (int r = 0; r < 4; ++r) acc[f][r] = 0.f;

            const uint32_t aAh = sb + O_XH + (m0 + (lane & 15)) * S128 + ((lane >> 4) * 8) * 2;
            const uint32_t aAl = sb + O_XL + (m0 + (lane & 15)) * S128 + ((lane >> 4) * 8) * 2;
            const uint32_t aB  = (uint32_t)(n0 + (lane & 7)) * S128 + (((lane >> 3) & 1) * 8) * 2;

            #pragma unroll
            for (int k = 0; k < 128; k += 16) {
                uint32_t ah[2][4], al[2][4], bh[3][2], bl[3][2];
                ldsm4(ah[0], aAh + k * 2);
                ldsm4(ah[1], aAh + k * 2 + 16 * S128);
                ldsm4(al[0], aAl + k * 2);
                ldsm4(al[1], aAl + k * 2 + 16 * S128);
                #pragma unroll
                for (int nt = 0; nt < 3; ++nt) {
                    ldsm2(bh[nt], sb + O_WH + aB + nt * 8 * S128 + k * 2);
                    ldsm2(bl[nt], sb + O_WL + aB + nt * 8 * S128 + k * 2);
                }
                #pragma unroll
                for (int mt = 0; mt < 2; ++mt)
                    #pragma unroll
                    for (int nt = 0; nt < 3; ++nt) {
                        mma16816(acc[mt * 3 + nt], ah[mt], bh[nt]);
                        mma16816(acc[mt * 3 + nt], ah[mt], bl[nt]);
                        mma16816(acc[mt * 3 + nt], al[mt], bh[nt]);
                    }
            }
            // epilogue: scatter to QT (scaled bf16), KT (bf16), VT (hi/lo, transposed)
            #pragma unroll
            for (int mt = 0; mt < 2; ++mt)
                #pragma unroll
                for (int nt = 0; nt < 3; ++nt)
                    #pragma unroll
                    for (int hf = 0; hf < 2; ++hf) {
                        int t = m0 + mt * 16 + hf * 8 + g;
                        #pragma unroll
                        for (int j = 0; j < 2; ++j) {
                            int n = n0 + nt * 8 + qj * 2 + j;
                            float v = acc[mt * 3 + nt][hf * 2 + j];
                            if (n < 32) {
                                *reinterpret_cast<__nv_bfloat16*>(sm + O_QT + t * S32 + n * 2)
                                    = __float2bfloat16(v * SCALE);
                            } else if (n < 64) {
                                *reinterpret_cast<__nv_bfloat16*>(sm + O_KT + t * S32 + (n - 32) * 2)
                                    = __float2bfloat16(v);
                            } else {
                                float hv, lv;
                                split2(v, hv, lv);
                                int d = n - 64;
                                *reinterpret_cast<__nv_bfloat16*>(sm + O_VTH + d * S128 + t * 2) = __float2bfloat16(hv);
                                *reinterpret_cast<__nv_bfloat16*>(sm + O_VTL + d * S128 + t * 2) = __float2bfloat16(lv);
                            }
                        }
                    }
        }
        __syncthreads();

        // ---- G2: S = Q K^T (M128 N128 K32, single pass) + causal softmax ----
        {
            const int m0 = wr * 32, n0 = wc * 32;
            float sc[8][4];
            #pragma unroll
            for (int f = 0; f < 8; ++f)
                #pragma unroll
                for (int r = 0; r < 4; ++r) sc[f][r] = 0.f;

            const uint32_t aA = sb + O_QT + (m0 + (lane & 15)) * S32 + ((lane >> 4) * 8) * 2;
            const uint32_t aB = sb + O_KT + (n0 + (lane & 7)) * S32 + (((lane >> 3) & 1) * 8) * 2;
            #pragma unroll
            for (int k = 0; k < 32; k += 16) {
                uint32_t qa[2][4], kb[4][2];
                ldsm4(qa[0], aA + k * 2);
                ldsm4(qa[1], aA + k * 2 + 16 * S32);
                #pragma unroll
                for (int nt = 0; nt < 4; ++nt)
                    ldsm2(kb[nt], aB + nt * 8 * S32 + k * 2);
                #pragma unroll
                for (int mt = 0; mt < 2; ++mt)
                    #pragma unroll
                    for (int nt = 0; nt < 4; ++nt)
                        mma16816(sc[mt * 4 + nt], qa[mt], kb[nt]);
            }

            // softmax: local (warp-slice) pass, exponentiate in place
            float* red = reinterpret_cast<float*>(sm + O_RED);
            float mloc[4], fac[4];
            #pragma unroll
            for (int ri = 0; ri < 4; ++ri) {
                int mt = ri >> 1, hf = ri & 1;
                int t = m0 + mt * 16 + hf * 8 + g;
                float mx = -3.0e38f;
                #pragma unroll
                for (int nt = 0; nt < 4; ++nt)
                    #pragma unroll
                    for (int j = 0; j < 2; ++j) {
                        int s = n0 + nt * 8 + qj * 2 + j;
                        float v = sc[mt * 4 + nt][hf * 2 + j];
                        if (s <= t) mx = fmaxf(mx, v);
                        else sc[mt * 4 + nt][hf * 2 + j] = -3.0e38f;
                    }
                mx = fmaxf(mx, __shfl_xor_sync(0xffffffffu, mx, 1));
                mx = fmaxf(mx, __shfl_xor_sync(0xffffffffu, mx, 2));
                float s = 0.f;
                #pragma unroll
                for (int nt = 0; nt < 4; ++nt)
                    #pragma unroll
                    for (int j = 0; j < 2; ++j) {
                        float v = sc[mt * 4 + nt][hf * 2 + j];
                        float e = (v > -1.0e38f) ? __expf(v - mx) : 0.f;
                        sc[mt * 4 + nt][hf * 2 + j] = e;
                        s += e;
                    }
                s += __shfl_xor_sync(0xffffffffu, s, 1);
                s += __shfl_xor_sync(0xffffffffu, s, 2);
                mloc[ri] = mx;
                if (qj == 0) {
                    red[(wc * 2 + 0) * 128 + t] = mx;
                    red[(wc * 2 + 1) * 128 + t] = s;
                }
            }
            __syncthreads();
            #pragma unroll
            for (int ri = 0; ri < 4; ++ri) {
                int mt = ri >> 1, hf = ri & 1;
                int t = m0 + mt * 16 + hf * 8 + g;
                float m = -3.0e38f;
                #pragma unroll
                for (int w4 = 0; w4 < 4; ++w4) m = fmaxf(m, red[(w4 * 2) * 128 + t]);
                float sum = 0.f;
                #pragma unroll
                for (int w4 = 0; w4 < 4; ++w4)
                    sum += red[(w4 * 2 + 1) * 128 + t] * __expf(red[(w4 * 2) * 128 + t] - m);
                fac[ri] = __expf(mloc[ri] - m) / sum;
            }
            // store P split (overwrites the W staging region; G1 is done)
            #pragma unroll
            for (int ri = 0; ri < 4; ++ri) {
                int mt = ri >> 1, hf = ri & 1;
                int t = m0 + mt * 16 + hf * 8 + g;
                #pragma unroll
                for (int nt = 0; nt < 4; ++nt) {
                    int s0 = n0 + nt * 8 + qj * 2;
                    float p0 = sc[mt * 4 + nt][hf * 2 + 0] * fac[ri];
                    float p1 = sc[mt * 4 + nt][hf * 2 + 1] * fac[ri];
                    float h0, l0, h1, l1;
                    split2(p0, h0, l0); split2(p1, h1, l1);
                    *reinterpret_cast<uint32_t*>(sm + O_PH + t * S128 + s0 * 2) = packbf(h0, h1);
                    *reinterpret_cast<uint32_t*>(sm + O_PL + t * S128 + s0 * 2) = packbf(l0, l1);
                }
            }
        }
        __syncthreads();

        // ---- G3: O = P V (M128 N32 K128, split 3-pass) ----
        {
            const int m0 = wr * 32, n0 = wc * 8;
            float oc[2][4];
            #pragma unroll
            for (int f = 0; f < 2; ++f)
                #pragma unroll
                for (int r = 0; r < 4; ++r) oc[f][r] = 0.f;

            const uint32_t aPh = sb + O_PH + (m0 + (lane & 15)) * S128 + ((lane >> 4) * 8) * 2;
            const uint32_t aPl = sb + O_PL + (m0 + (lane & 15)) * S128 + ((lane >> 4) * 8) * 2;
            const uint32_t aV  = (uint32_t)(n0 + (lane & 7)) * S128 + (((lane >> 3) & 1) * 8) * 2;
            #pragma unroll
            for (int k = 0; k < 128; k += 16) {
                uint32_t ph[2][4], pl[2][4], vh[2], vl[2];
                ldsm4(ph[0], aPh + k * 2);
                ldsm4(ph[1], aPh + k * 2 + 16 * S128);
                ldsm4(pl[0], aPl + k * 2);
                ldsm4(pl[1], aPl + k * 2 + 16 * S128);
                ldsm2(vh, sb + O_VTH + aV + k * 2);
                ldsm2(vl, sb + O_VTL + aV + k * 2);
                #pragma unroll
                for (int mt = 0; mt < 2; ++mt) {
                    mma16816(oc[mt], ph[mt], vh);
                    mma16816(oc[mt], ph[mt], vl);
                    mma16816(oc[mt], pl[mt], vh);
                }
            }
            // epilogue: O hi/lo [t][d]
            #pragma unroll
            for (int mt = 0; mt < 2; ++mt)
                #pragma unroll
                for (int hf = 0; hf < 2; ++hf) {
                    int t = m0 + mt * 16 + hf * 8 + g;
                    int d0 = n0 + qj * 2;
                    float h0, l0, h1, l1;
                    split2(oc[mt][hf * 2 + 0], h0, l0);
                    split2(oc[mt][hf * 2 + 1], h1, l1);
                    *reinterpret_cast<uint32_t*>(sm + O_OH + t * S32 + d0 * 2) = packbf(h0, h1);
                    *reinterpret_cast<uint32_t*>(sm + O_OL + t * S32 + d0 * 2) = packbf(l0, l1);
                }
        }
        __syncthreads();

        // ---- G4: OUT += O Wp^T (M128 N128 K32, split 3-pass, reg-persistent) ----
        {
            const int m0 = wr * 32, n0 = wc * 32;
            const uint32_t aOh = sb + O_OH + (m0 + (lane & 15)) * S32 + ((lane >> 4) * 8) * 2;
            const uint32_t aOl = sb + O_OL + (m0 + (lane & 15)) * S32 + ((lane >> 4) * 8) * 2;
            const uint32_t aW  = (uint32_t)(n0 + (lane & 7)) * S32 + (((lane >> 3) & 1) * 8) * 2;
            #pragma unroll
            for (int k = 0; k < 32; k += 16) {
                uint32_t oh[2][4], ol[2][4], wh[4][2], wl[4][2];
                ldsm4(oh[0], aOh + k * 2);
                ldsm4(oh[1], aOh + k * 2 + 16 * S32);
                ldsm4(ol[0], aOl + k * 2);
                ldsm4(ol[1], aOl + k * 2 + 16 * S32);
                #pragma unroll
                for (int nt = 0; nt < 4; ++nt) {
                    ldsm2(wh[nt], sb + O_WPH + aW + nt * 8 * S32 + k * 2);
                    ldsm2(wl[nt], sb + O_WPL + aW + nt * 8 * S32 + k * 2);
                }
                #pragma unroll
                for (int mt = 0; mt < 2; ++mt)
                    #pragma unroll
                    for (int nt = 0; nt < 4; ++nt) {
                        mma16816(oacc[mt * 4 + nt], oh[mt], wh[nt]);
                        mma16816(oacc[mt * 4 + nt], oh[mt], wl[nt]);
                        mma16816(oacc[mt * 4 + nt], ol[mt], wh[nt]);
                    }
            }
        }
        __syncthreads();   // next head's staging overwrites W/Wp regions
    }

    // ---- final store: out = oacc + bp ----
    {
        const int m0 = wr * 32, n0 = wc * 32;
        #pragma unroll
        for (int mt = 0; mt < 2; ++mt)
            #pragma unroll
            for (int nt = 0; nt < 4; ++nt) {
                int c = n0 + nt * 8 + qj * 2;
                float2 bv = *reinterpret_cast<const float2*>(bp + c);
                #pragma unroll
                for (int hf = 0; hf < 2; ++hf) {
                    int t = m0 + mt * 16 + hf * 8 + g;
                    float2 v;
                    v.x = oacc[mt * 4 + nt][hf * 2 + 0] + bv.x;
                    v.y = oacc[mt * 4 + nt][hf * 2 + 1] + bv.y;
                    *reinterpret_cast<float2*>(out + ((size_t)b * 128 + t) * 128 + c) = v;
                }
            }
    }
}

extern "C" void kernel_launch(void* const* d_in, const int* in_sizes, int n_in,
                              void* d_out, int out_size)
{
    (void)in_sizes; (void)n_in; (void)out_size;
    const float* x  = (const float*)d_in[0];
    const float* Wq = (const float*)d_in[1];
    const float* Wk = (const float*)d_in[2];
    const float* Wv = (const float*)d_in[3];
    const float* Wp = (const float*)d_in[4];
    const float* bp = (const float*)d_in[5];
    float* out = (float*)d_out;

    cudaFuncSetAttribute(mha_mma_kernel,
                         cudaFuncAttributeMaxDynamicSharedMemorySize, SMEM_BYTES);
    mha_mma_kernel<<<NB, 512, SMEM_BYTES>>>(x, Wq, Wk, Wv, Wp, bp, out);
}

// round 12
// speedup vs baseline: 1.9988x; 1.3484x over previous
#include <cuda_runtime.h>
#include <cuda_bf16.h>
#include <cstdint>

// MHA B=4096,T=128,C=128,H=4,D=32 causal, scale=C^-0.5
// Warp-level mma.sync (bf16, fp32 accum) with hi/lo split precision.
// 1 CTA per batch, 512 threads = 16 warps (4x4 warp grid).
// R12: conflict-free vectorized staging/epilogues, ldmatrix.trans for W (G1) and V (G3).

#define NB 4096
#define SCALE 0.08838834764831845f

// smem row strides (bytes)
#define S128 272   // 128 bf16 rows (256B) + 16 pad
#define SW   208   // 96 bf16 rows (192B) + 16 pad
#define S32  80    // 32 bf16 rows (64B) + 16 pad

// smem byte offsets
#define O_XH   0                  // x hi  [128 t][128 c] bf16, stride S128
#define O_XL   34816
#define O_PH   69632              // P hi [128 t][128 s]  (union with WB)
#define O_PL   104448
#define O_WBH  69632              // W hi [128 c][96 n] stride SW (n = m*32+d)
#define O_WBL  96256
#define O_QT   139264             // Q bf16 [128 t][32 d] stride S32 (pre-scaled)
#define O_KT   149504             // K bf16 [128 s][32 d]
#define O_VH   159744             // V hi [128 s][32 d]
#define O_VL   169984
#define O_OH   180224             // O hi [128 t][32 d]
#define O_OL   190464
#define O_WPH  200704             // Wp hi [128 c][32 d]
#define O_WPL  210944
#define O_RED  221184             // float [4 wc][2][128]
#define SMEM_BYTES 225280

__device__ __forceinline__ uint32_t cvta_s(const void* p) {
    uint32_t a;
    asm("{ .reg .u64 t; cvta.to.shared.u64 t, %1; cvt.u32.u64 %0, t; }" : "=r"(a) : "l"(p));
    return a;
}
__device__ __forceinline__ void ldsm4(uint32_t* r, uint32_t a) {
    asm volatile("ldmatrix.sync.aligned.m8n8.x4.shared.b16 {%0,%1,%2,%3}, [%4];"
                 : "=r"(r[0]), "=r"(r[1]), "=r"(r[2]), "=r"(r[3]) : "r"(a));
}
__device__ __forceinline__ void ldsm2(uint32_t* r, uint32_t a) {
    asm volatile("ldmatrix.sync.aligned.m8n8.x2.shared.b16 {%0,%1}, [%2];"
                 : "=r"(r[0]), "=r"(r[1]) : "r"(a));
}
__device__ __forceinline__ void ldsm2t(uint32_t* r, uint32_t a) {
    asm volatile("ldmatrix.sync.aligned.m8n8.x2.trans.shared.b16 {%0,%1}, [%2];"
                 : "=r"(r[0]), "=r"(r[1]) : "r"(a));
}
__device__ __forceinline__ void mma16816(float* c, const uint32_t* a, const uint32_t* b) {
    asm volatile("mma.sync.aligned.m16n8k16.row.col.f32.bf16.bf16.f32 "
                 "{%0,%1,%2,%3}, {%4,%5,%6,%7}, {%8,%9}, {%0,%1,%2,%3};"
                 : "+f"(c[0]), "+f"(c[1]), "+f"(c[2]), "+f"(c[3])
                 : "r"(a[0]), "r"(a[1]), "r"(a[2]), "r"(a[3]), "r"(b[0]), "r"(b[1]));
}
// pack two floats as bf16x2: first arg -> lower half
__device__ __forceinline__ uint32_t packbf(float lo, float hi) {
    uint32_t d;
    asm("cvt.rn.bf16x2.f32 %0, %1, %2;" : "=r"(d) : "f"(hi), "f"(lo));
    return d;
}
__device__ __forceinline__ void split2(float v, float& h, float& l) {
    __nv_bfloat16 hb = __float2bfloat16(v);
    h = __bfloat162float(hb);
    l = v - h;
}
// split a float2 and store hi-pair/lo-pair as u32 at (hiOff|loOff) + boff
__device__ __forceinline__ void st_split2(char* sm_, uint32_t hiOff, uint32_t loOff,
                                          uint32_t boff, float v0, float v1) {
    float h0, l0, h1, l1;
    split2(v0, h0, l0); split2(v1, h1, l1);
    *reinterpret_cast<uint32_t*>(sm_ + hiOff + boff) = packbf(h0, h1);
    *reinterpret_cast<uint32_t*>(sm_ + loOff + boff) = packbf(l0, l1);
}

__global__ void __launch_bounds__(512, 1)
mha_mma_kernel(const float* __restrict__ x,
               const float* __restrict__ Wq,
               const float* __restrict__ Wk,
               const float* __restrict__ Wv,
               const float* __restrict__ Wp,
               const float* __restrict__ bp,
               float* __restrict__ out)
{
    extern __shared__ char sm[];
    const uint32_t sb = cvta_s(sm);
    const int tid  = threadIdx.x;
    const int lane = tid & 31;
    const int warp = tid >> 5;
    const int wr   = warp >> 2;      // warp row group (m0 = wr*32)
    const int wc   = warp & 3;       // warp col group
    const int g    = lane >> 2;      // fragment row within 8
    const int qj   = lane & 3;       // fragment col quad
    const int b    = blockIdx.x;

    // ---- stage x -> XH/XL ; bank = 4*perm(t) + qj (conflict-free) ----
    {
        int t = tid >> 2, q4 = tid & 3;
        const float* xr = x + ((size_t)b * 128 + t) * 128;
        uint32_t base = (uint32_t)t * S128;
        #pragma unroll
        for (int i = 0; i < 16; ++i) {
            int c = 2 * q4 + 8 * i;
            float2 v = *reinterpret_cast<const float2*>(xr + c);
            st_split2(sm, O_XH, O_XL, base + c * 2, v.x, v.y);
        }
    }

    float oacc[8][4];   // persistent out fragments (2 mt x 4 nt)
    #pragma unroll
    for (int f = 0; f < 8; ++f)
        #pragma unroll
        for (int r = 0; r < 4; ++r) oacc[f][r] = 0.f;

    for (int h = 0; h < 4; ++h) {
        // ---- stage W (untransposed [c][n], n=m*32+d) and Wp slice [c][d] ----
        {
            int c = tid >> 2, q4 = tid & 3;
            #pragma unroll
            for (int m = 0; m < 3; ++m) {
                const float* w = ((m == 0) ? Wq : (m == 1) ? Wk : Wv)
                                 + ((size_t)h * 128 + c) * 32;
                uint32_t base = (uint32_t)c * SW + m * 64;
                #pragma unroll
                for (int i = 0; i < 4; ++i) {
                    int d = 2 * q4 + 8 * i;
                    float2 v = *reinterpret_cast<const float2*>(w + d);
                    st_split2(sm, O_WBH, O_WBL, base + d * 2, v.x, v.y);
                }
            }
            const float* wp = Wp + (size_t)c * 128 + h * 32;
            uint32_t base = (uint32_t)c * S32;
            #pragma unroll
            for (int i = 0; i < 4; ++i) {
                int d = 2 * q4 + 8 * i;
                float2 v = *reinterpret_cast<const float2*>(wp + d);
                st_split2(sm, O_WPH, O_WPL, base + d * 2, v.x, v.y);
            }
        }
        __syncthreads();

        // ---- G1: QKV[t][n] = sum_c x[t][c]*W[c][n]  M128 N96 K128, split 3-pass ----
        {
            const int m0 = wr * 32, n0 = wc * 24;
            float acc[6][4];
            #pragma unroll
            for (int f = 0; f < 6; ++f)
                #pragma unroll
                for (int r = 0; r < 4; ++r) acc[f][r] = 0.f;

            const uint32_t aAh = sb + O_XH + (m0 + (lane & 15)) * S128 + ((lane >> 4) * 8) * 2;
            const uint32_t aAl = sb + O_XL + (m0 + (lane & 15)) * S128 + ((lane >> 4) * 8) * 2;
            // trans B: rows c = k + (lane&15), col offset n0
            const uint32_t aBt = (uint32_t)(lane & 15) * SW + n0 * 2;

            #pragma unroll
            for (int k = 0; k < 128; k += 16) {
                uint32_t ah[2][4], al[2][4], bh[3][2], bl[3][2];
                ldsm4(ah[0], aAh + k * 2);
                ldsm4(ah[1], aAh + k * 2 + 16 * S128);
                ldsm4(al[0], aAl + k * 2);
                ldsm4(al[1], aAl + k * 2 + 16 * S128);
                #pragma unroll
                for (int nt = 0; nt < 3; ++nt) {
                    ldsm2t(bh[nt], sb + O_WBH + aBt + k * SW + nt * 16);
                    ldsm2t(bl[nt], sb + O_WBL + aBt + k * SW + nt * 16);
                }
                #pragma unroll
                for (int mt = 0; mt < 2; ++mt)
                    #pragma unroll
                    for (int nt = 0; nt < 3; ++nt) {
                        mma16816(acc[mt * 3 + nt], ah[mt], bh[nt]);
                        mma16816(acc[mt * 3 + nt], ah[mt], bl[nt]);
                        mma16816(acc[mt * 3 + nt], al[mt], bh[nt]);
                    }
            }
            // epilogue: Q (scaled bf16), K (bf16), V (hi/lo) — all u32-packed, [row][d]
            #pragma unroll
            for (int mt = 0; mt < 2; ++mt)
                #pragma unroll
                for (int nt = 0; nt < 3; ++nt) {
                    int nb = n0 + nt * 8;     // 8-block fully inside one dest
                    #pragma unroll
                    for (int hf = 0; hf < 2; ++hf) {
                        int t = m0 + mt * 16 + hf * 8 + g;
                        float v0 = acc[mt * 3 + nt][hf * 2 + 0];
                        float v1 = acc[mt * 3 + nt][hf * 2 + 1];
                        int n = nb + qj * 2;
                        if (nb < 32) {
                            *reinterpret_cast<uint32_t*>(sm + O_QT + t * S32 + n * 2)
                                = packbf(v0 * SCALE, v1 * SCALE);
                        } else if (nb < 64) {
                            *reinterpret_cast<uint32_t*>(sm + O_KT + t * S32 + (n - 32) * 2)
                                = packbf(v0, v1);
                        } else {
                            st_split2(sm, O_VH, O_VL, (uint32_t)(t * S32 + (n - 64) * 2), v0, v1);
                        }
                    }
                }
        }
        __syncthreads();

        // ---- G2: S = Q K^T (M128 N128 K32) + causal softmax ----
        {
            const int m0 = wr * 32, n0 = wc * 32;
            float sc[8][4];
            #pragma unroll
            for (int f = 0; f < 8; ++f)
                #pragma unroll
                for (int r = 0; r < 4; ++r) sc[f][r] = 0.f;

            const uint32_t aA = sb + O_QT + (m0 + (lane & 15)) * S32 + ((lane >> 4) * 8) * 2;
            const uint32_t aB = sb + O_KT + (n0 + (lane & 7)) * S32 + (((lane >> 3) & 1) * 8) * 2;
            #pragma unroll
            for (int k = 0; k < 32; k += 16) {
                uint32_t qa[2][4], kb[4][2];
                ldsm4(qa[0], aA + k * 2);
                ldsm4(qa[1], aA + k * 2 + 16 * S32);
                #pragma unroll
                for (int nt = 0; nt < 4; ++nt)
                    ldsm2(kb[nt], aB + nt * 8 * S32 + k * 2);
                #pragma unroll
                for (int mt = 0; mt < 2; ++mt)
                    #pragma unroll
                    for (int nt = 0; nt < 4; ++nt)
                        mma16816(sc[mt * 4 + nt], qa[mt], kb[nt]);
            }

            float* red = reinterpret_cast<float*>(sm + O_RED);
            float mloc[4], fac[4];
            #pragma unroll
            for (int ri = 0; ri < 4; ++ri) {
                int mt = ri >> 1, hf = ri & 1;
                int t = m0 + mt * 16 + hf * 8 + g;
                float mx = -3.0e38f;
                #pragma unroll
                for (int nt = 0; nt < 4; ++nt)
                    #pragma unroll
                    for (int j = 0; j < 2; ++j) {
                        int s = n0 + nt * 8 + qj * 2 + j;
                        float v = sc[mt * 4 + nt][hf * 2 + j];
                        if (s <= t) mx = fmaxf(mx, v);
                        else sc[mt * 4 + nt][hf * 2 + j] = -3.0e38f;
                    }
                mx = fmaxf(mx, __shfl_xor_sync(0xffffffffu, mx, 1));
                mx = fmaxf(mx, __shfl_xor_sync(0xffffffffu, mx, 2));
                float s = 0.f;
                #pragma unroll
                for (int nt = 0; nt < 4; ++nt)
                    #pragma unroll
                    for (int j = 0; j < 2; ++j) {
                        float v = sc[mt * 4 + nt][hf * 2 + j];
                        float e = (v > -1.0e38f) ? __expf(v - mx) : 0.f;
                        sc[mt * 4 + nt][hf * 2 + j] = e;
                        s += e;
                    }
                s += __shfl_xor_sync(0xffffffffu, s, 1);
                s += __shfl_xor_sync(0xffffffffu, s, 2);
                mloc[ri] = mx;
                if (qj == 0) {
                    red[(wc * 2 + 0) * 128 + t] = mx;
                    red[(wc * 2 + 1) * 128 + t] = s;
                }
            }
            __syncthreads();
            #pragma unroll
            for (int ri = 0; ri < 4; ++ri) {
                int mt = ri >> 1, hf = ri & 1;
                int t = m0 + mt * 16 + hf * 8 + g;
                float m = -3.0e38f;
                #pragma unroll
                for (int w4 = 0; w4 < 4; ++w4) m = fmaxf(m, red[(w4 * 2) * 128 + t]);
                float sum = 0.f;
                #pragma unroll
                for (int w4 = 0; w4 < 4; ++w4)
                    sum += red[(w4 * 2 + 1) * 128 + t] * __expf(red[(w4 * 2) * 128 + t] - m);
                fac[ri] = __expf(mloc[ri] - m) / sum;
            }
            // store P split (overwrites the W staging region; G1 done)
            #pragma unroll
            for (int ri = 0; ri < 4; ++ri) {
                int mt = ri >> 1, hf = ri & 1;
                int t = m0 + mt * 16 + hf * 8 + g;
                #pragma unroll
                for (int nt = 0; nt < 4; ++nt) {
                    int s0 = n0 + nt * 8 + qj * 2;
                    st_split2(sm, O_PH, O_PL, (uint32_t)(t * S128 + s0 * 2),
                              sc[mt * 4 + nt][hf * 2 + 0] * fac[ri],
                              sc[mt * 4 + nt][hf * 2 + 1] * fac[ri]);
                }
            }
        }
        __syncthreads();

        // ---- G3: O = P V (M128 N32 K128, split 3-pass, trans-B from V[s][d]) ----
        {
            const int m0 = wr * 32, n0 = wc * 8;
            float oc[2][4];
            #pragma unroll
            for (int f = 0; f < 2; ++f)
                #pragma unroll
                for (int r = 0; r < 4; ++r) oc[f][r] = 0.f;

            const uint32_t aPh = sb + O_PH + (m0 + (lane & 15)) * S128 + ((lane >> 4) * 8) * 2;
            const uint32_t aPl = sb + O_PL + (m0 + (lane & 15)) * S128 + ((lane >> 4) * 8) * 2;
            const uint32_t aVt = (uint32_t)(lane & 15) * S32 + n0 * 2;   // rows s=k+(lane&15)
            #pragma unroll
            for (int k = 0; k < 128; k += 16) {
                uint32_t ph[2][4], pl[2][4], vh[2], vl[2];
                ldsm4(ph[0], aPh + k * 2);
                ldsm4(ph[1], aPh + k * 2 + 16 * S128);
                ldsm4(pl[0], aPl + k * 2);
                ldsm4(pl[1], aPl + k * 2 + 16 * S128);
                ldsm2t(vh, sb + O_VH + aVt + k * S32);
                ldsm2t(vl, sb + O_VL + aVt + k * S32);
                #pragma unroll
                for (int mt = 0; mt < 2; ++mt) {
                    mma16816(oc[mt], ph[mt], vh);
                    mma16816(oc[mt], ph[mt], vl);
                    mma16816(oc[mt], pl[mt], vh);
                }
            }
            #pragma unroll
            for (int mt = 0; mt < 2; ++mt)
                #pragma unroll
                for (int hf = 0; hf < 2; ++hf) {
                    int t = m0 + mt * 16 + hf * 8 + g;
                    int d0 = n0 + qj * 2;
                    st_split2(sm, O_OH, O_OL, (uint32_t)(t * S32 + d0 * 2),
                              oc[mt][hf * 2 + 0], oc[mt][hf * 2 + 1]);
                }
        }
        __syncthreads();

        // ---- G4: OUT += O Wp^T (M128 N128 K32, split 3-pass, reg-persistent) ----
        {
            const int m0 = wr * 32, n0 = wc * 32;
            const uint32_t aOh = sb + O_OH + (m0 + (lane & 15)) * S32 + ((lane >> 4) * 8) * 2;
            const uint32_t aOl = sb + O_OL + (m0 + (lane & 15)) * S32 + ((lane >> 4) * 8) * 2;
            const uint32_t aW  = (uint32_t)(n0 + (lane & 7)) * S32 + (((lane >> 3) & 1) * 8) * 2;
            #pragma unroll
            for (int k = 0; k < 32; k += 16) {
                uint32_t oh[2][4], ol[2][4], wh[4][2], wl[4][2];
                ldsm4(oh[0], aOh + k * 2);
                ldsm4(oh[1], aOh + k * 2 + 16 * S32);
                ldsm4(ol[0], aOl + k * 2);
                ldsm4(ol[1], aOl + k * 2 + 16 * S32);
                #pragma unroll
                for (int nt = 0; nt < 4; ++nt) {
                    ldsm2(wh[nt], sb + O_WPH + aW + nt * 8 * S32 + k * 2);
                    ldsm2(wl[nt], sb + O_WPL + aW + nt * 8 * S32 + k * 2);
                }
                #pragma unroll
                for (int mt = 0; mt < 2; ++mt)
                    #pragma unroll
                    for (int nt = 0; nt < 4; ++nt) {
                        mma16816(oacc[mt * 4 + nt], oh[mt], wh[nt]);
                        mma16816(oacc[mt * 4 + nt], oh[mt], wl[nt]);
                        mma16816(oacc[mt * 4 + nt], ol[mt], wh[nt]);
                    }
            }
        }
        __syncthreads();   // next head's staging overwrites W/Wp regions
    }

    // ---- final store: out = oacc + bp ----
    {
        const int m0 = wr * 32, n0 = wc * 32;
        #pragma unroll
        for (int mt = 0; mt < 2; ++mt)
            #pragma unroll
            for (int nt = 0; nt < 4; ++nt) {
                int c = n0 + nt * 8 + qj * 2;
                float2 bv = *reinterpret_cast<const float2*>(bp + c);
                #pragma unroll
                for (int hf = 0; hf < 2; ++hf) {
                    int t = m0 + mt * 16 + hf * 8 + g;
                    float2 v;
                    v.x = oacc[mt * 4 + nt][hf * 2 + 0] + bv.x;
                    v.y = oacc[mt * 4 + nt][hf * 2 + 1] + bv.y;
                    *reinterpret_cast<float2*>(out + ((size_t)b * 128 + t) * 128 + c) = v;
                }
            }
    }
}

extern "C" void kernel_launch(void* const* d_in, const int* in_sizes, int n_in,
                              void* d_out, int out_size)
{
    (void)in_sizes; (void)n_in; (void)out_size;
    const float* x  = (const float*)d_in[0];
    const float* Wq = (const float*)d_in[1];
    const float* Wk = (const float*)d_in[2];
    const float* Wv = (const float*)d_in[3];
    const float* Wp = (const float*)d_in[4];
    const float* bp = (const float*)d_in[5];
    float* out = (float*)d_out;

    cudaFuncSetAttribute(mha_mma_kernel,
                         cudaFuncAttributeMaxDynamicSharedMemorySize, SMEM_BYTES);
    mha_mma_kernel<<<NB, 512, SMEM_BYTES>>>(x, Wq, Wk, Wv, Wp, bp, out);
}

// round 15
// speedup vs baseline: 2.2038x; 1.1026x over previous
#include <cuda_runtime.h>
#include <cuda_bf16.h>
#include <cstdint>

// MHA B=4096,T=128,C=128,H=4,D=32 causal, scale=C^-0.5
// Warp-level mma.sync (bf16, fp32 accum) with hi/lo split precision.
// 1 CTA per batch, 512 threads = 16 warps (4x4 warp grid).
// R13: causal skips (G2 dead warps, G3 bounded k-loop), ldmatrix.x4 everywhere.

#define NB 4096
#define SCALE 0.08838834764831845f

// smem row strides (bytes)
#define S128 272   // 128 bf16 rows (256B) + 16 pad
#define SW   208   // 96 bf16 rows (192B) + 16 pad
#define S32  80    // 32 bf16 rows (64B) + 16 pad

// smem byte offsets
#define O_XH   0                  // x hi  [128 t][128 c] bf16, stride S128
#define O_XL   34816
#define O_PH   69632              // P hi [128 t][128 s]  (union with WB)
#define O_PL   104448
#define O_WBH  69632              // W hi [128 c][96 n] stride SW (n = m*32+d)
#define O_WBL  96256
#define O_QT   139264             // Q bf16 [128 t][32 d] stride S32 (pre-scaled)
#define O_KT   149504             // K bf16 [128 s][32 d]
#define O_VH   159744             // V hi [128 s][32 d]
#define O_VL   169984
#define O_OH   180224             // O hi [128 t][32 d]
#define O_OL   190464
#define O_WPH  200704             // Wp hi [128 c][32 d]
#define O_WPL  210944
#define O_RED  221184             // float [4 wc][2][128]
#define SMEM_BYTES 225280

__device__ __forceinline__ uint32_t cvta_s(const void* p) {
    uint32_t a;
    asm("{ .reg .u64 t; cvta.to.shared.u64 t, %1; cvt.u32.u64 %0, t; }" : "=r"(a) : "l"(p));
    return a;
}
__device__ __forceinline__ void ldsm4(uint32_t* r, uint32_t a) {
    asm volatile("ldmatrix.sync.aligned.m8n8.x4.shared.b16 {%0,%1,%2,%3}, [%4];"
                 : "=r"(r[0]), "=r"(r[1]), "=r"(r[2]), "=r"(r[3]) : "r"(a));
}
__device__ __forceinline__ void ldsm2t(uint32_t* r, uint32_t a) {
    asm volatile("ldmatrix.sync.aligned.m8n8.x2.trans.shared.b16 {%0,%1}, [%2];"
                 : "=r"(r[0]), "=r"(r[1]) : "r"(a));
}
__device__ __forceinline__ void ldsm4t(uint32_t* r, uint32_t a) {
    asm volatile("ldmatrix.sync.aligned.m8n8.x4.trans.shared.b16 {%0,%1,%2,%3}, [%4];"
                 : "=r"(r[0]), "=r"(r[1]), "=r"(r[2]), "=r"(r[3]) : "r"(a));
}
__device__ __forceinline__ void mma16816(float* c, const uint32_t* a, const uint32_t* b) {
    asm volatile("mma.sync.aligned.m16n8k16.row.col.f32.bf16.bf16.f32 "
                 "{%0,%1,%2,%3}, {%4,%5,%6,%7}, {%8,%9}, {%0,%1,%2,%3};"
                 : "+f"(c[0]), "+f"(c[1]), "+f"(c[2]), "+f"(c[3])
                 : "r"(a[0]), "r"(a[1]), "r"(a[2]), "r"(a[3]), "r"(b[0]), "r"(b[1]));
}
__device__ __forceinline__ uint32_t packbf(float lo, float hi) {
    uint32_t d;
    asm("cvt.rn.bf16x2.f32 %0, %1, %2;" : "=r"(d) : "f"(hi), "f"(lo));
    return d;
}
__device__ __forceinline__ void split2(float v, float& h, float& l) {
    __nv_bfloat16 hb = __float2bfloat16(v);
    h = __bfloat162float(hb);
    l = v - h;
}
__device__ __forceinline__ void st_split2(char* sm_, uint32_t hiOff, uint32_t loOff,
                                          uint32_t boff, float v0, float v1) {
    float h0, l0, h1, l1;
    split2(v0, h0, l0); split2(v1, h1, l1);
    *reinterpret_cast<uint32_t*>(sm_ + hiOff + boff) = packbf(h0, h1);
    *reinterpret_cast<uint32_t*>(sm_ + loOff + boff) = packbf(l0, l1);
}

__global__ void __launch_bounds__(512, 1)
mha_mma_kernel(const float* __restrict__ x,
               const float* __restrict__ Wq,
               const float* __restrict__ Wk,
               const float* __restrict__ Wv,
               const float* __restrict__ Wp,
               const float* __restrict__ bp,
               float* __restrict__ out)
{
    extern __shared__ char sm[];
    const uint32_t sb = cvta_s(sm);
    const int tid  = threadIdx.x;
    const int lane = tid & 31;
    const int warp = tid >> 5;
    const int wr   = warp >> 2;      // warp row group (m0 = wr*32)
    const int wc   = warp & 3;       // warp col group
    const int g    = lane >> 2;      // fragment row within 8
    const int qj   = lane & 3;       // fragment col quad
    const int b    = blockIdx.x;

    // ---- stage x -> XH/XL (conflict-free u32 stores) ----
    {
        int t = tid >> 2, q4 = tid & 3;
        const float* xr = x + ((size_t)b * 128 + t) * 128;
        uint32_t base = (uint32_t)t * S128;
        #pragma unroll
        for (int i = 0; i < 16; ++i) {
            int c = 2 * q4 + 8 * i;
            float2 v = *reinterpret_cast<const float2*>(xr + c);
            st_split2(sm, O_XH, O_XL, base + c * 2, v.x, v.y);
        }
    }

    float oacc[8][4];   // persistent out fragments (2 mt x 4 nt)
    #pragma unroll
    for (int f = 0; f < 8; ++f)
        #pragma unroll
        for (int r = 0; r < 4; ++r) oacc[f][r] = 0.f;

    for (int h = 0; h < 4; ++h) {
        // ---- stage W [c][n] (n=m*32+d) and Wp slice [c][d] ----
        {
            int c = tid >> 2, q4 = tid & 3;
            #pragma unroll
            for (int m = 0; m < 3; ++m) {
                const float* w = ((m == 0) ? Wq : (m == 1) ? Wk : Wv)
                                 + ((size_t)h * 128 + c) * 32;
                uint32_t base = (uint32_t)c * SW + m * 64;
                #pragma unroll
                for (int i = 0; i < 4; ++i) {
                    int d = 2 * q4 + 8 * i;
                    float2 v = *reinterpret_cast<const float2*>(w + d);
                    st_split2(sm, O_WBH, O_WBL, base + d * 2, v.x, v.y);
                }
            }
            const float* wp = Wp + (size_t)c * 128 + h * 32;
            uint32_t base = (uint32_t)c * S32;
            #pragma unroll
            for (int i = 0; i < 4; ++i) {
                int d = 2 * q4 + 8 * i;
                float2 v = *reinterpret_cast<const float2*>(wp + d);
                st_split2(sm, O_WPH, O_WPL, base + d * 2, v.x, v.y);
            }
        }
        __syncthreads();

        // ---- G1: QKV[t][n] = sum_c x[t][c]*W[c][n]  M128 N96 K128, split 3-pass ----
        {
            const int m0 = wr * 32, n0 = wc * 24;
            float acc[6][4];
            #pragma unroll
            for (int f = 0; f < 6; ++f)
                #pragma unroll
                for (int r = 0; r < 4; ++r) acc[f][r] = 0.f;

            const uint32_t aAh = sb + O_XH + (m0 + (lane & 15)) * S128 + ((lane >> 4) * 8) * 2;
            const uint32_t aAl = sb + O_XL + (m0 + (lane & 15)) * S128 + ((lane >> 4) * 8) * 2;
            // trans B x4: lanes 0-15 rows k.., col n0; lanes 16-31 rows k.., col n0+8
            const uint32_t aB4 = (uint32_t)(lane & 15) * SW + (n0 + (lane >> 4) * 8) * 2;
            const uint32_t aB2 = (uint32_t)(lane & 15) * SW + (n0 + 16) * 2;

            #pragma unroll
            for (int k = 0; k < 128; k += 16) {
                uint32_t ah[2][4], al[2][4], bh[3][2], bl[3][2];
                ldsm4(ah[0], aAh + k * 2);
                ldsm4(ah[1], aAh + k * 2 + 16 * S128);
                ldsm4(al[0], aAl + k * 2);
                ldsm4(al[1], aAl + k * 2 + 16 * S128);
                ldsm4t(&bh[0][0], sb + O_WBH + aB4 + k * SW);   // nt0,nt1
                ldsm2t(bh[2],     sb + O_WBH + aB2 + k * SW);   // nt2
                ldsm4t(&bl[0][0], sb + O_WBL + aB4 + k * SW);
                ldsm2t(bl[2],     sb + O_WBL + aB2 + k * SW);
                #pragma unroll
                for (int mt = 0; mt < 2; ++mt)
                    #pragma unroll
                    for (int nt = 0; nt < 3; ++nt) {
                        mma16816(acc[mt * 3 + nt], ah[mt], bh[nt]);
                        mma16816(acc[mt * 3 + nt], ah[mt], bl[nt]);
                        mma16816(acc[mt * 3 + nt], al[mt], bh[nt]);
                    }
            }
            // epilogue: Q (scaled bf16), K (bf16), V (hi/lo) — u32-packed
            #pragma unroll
            for (int mt = 0; mt < 2; ++mt)
                #pragma unroll
                for (int nt = 0; nt < 3; ++nt) {
                    int nb = n0 + nt * 8;
                    #pragma unroll
                    for (int hf = 0; hf < 2; ++hf) {
                        int t = m0 + mt * 16 + hf * 8 + g;
                        float v0 = acc[mt * 3 + nt][hf * 2 + 0];
                        float v1 = acc[mt * 3 + nt][hf * 2 + 1];
                        int n = nb + qj * 2;
                        if (nb < 32) {
                            *reinterpret_cast<uint32_t*>(sm + O_QT + t * S32 + n * 2)
                                = packbf(v0 * SCALE, v1 * SCALE);
                        } else if (nb < 64) {
                            *reinterpret_cast<uint32_t*>(sm + O_KT + t * S32 + (n - 32) * 2)
                                = packbf(v0, v1);
                        } else {
                            st_split2(sm, O_VH, O_VL, (uint32_t)(t * S32 + (n - 64) * 2), v0, v1);
                        }
                    }
                }
        }
        __syncthreads();

        // ---- G2: S = Q K^T (M128 N128 K32) + causal softmax ----
        {
            const int m0 = wr * 32, n0 = wc * 32;
            const bool dead = (wc > wr);       // tile fully above diagonal
            float* red = reinterpret_cast<float*>(sm + O_RED);
            float sc[8][4];
            float mloc[4], fac[4];

            if (!dead) {
                #pragma unroll
                for (int f = 0; f < 8; ++f)
                    #pragma unroll
                    for (int r = 0; r < 4; ++r) sc[f][r] = 0.f;

                const uint32_t aA  = sb + O_QT + (m0 + (lane & 15)) * S32 + ((lane >> 4) * 8) * 2;
                const uint32_t aB4 = sb + O_KT
                    + (n0 + (lane >> 4) * 8 + (lane & 7)) * S32 + (((lane >> 3) & 1) * 8) * 2;
                #pragma unroll
                for (int k = 0; k < 32; k += 16) {
                    uint32_t qa[2][4], kb[4][2];
                    ldsm4(qa[0], aA + k * 2);
                    ldsm4(qa[1], aA + k * 2 + 16 * S32);
                    ldsm4(&kb[0][0], aB4 + k * 2);              // nt0,nt1
                    ldsm4(&kb[2][0], aB4 + 16 * S32 + k * 2);   // nt2,nt3
                    #pragma unroll
                    for (int mt = 0; mt < 2; ++mt)
                        #pragma unroll
                        for (int nt = 0; nt < 4; ++nt)
                            mma16816(sc[mt * 4 + nt], qa[mt], kb[nt]);
                }

                #pragma unroll
                for (int ri = 0; ri < 4; ++ri) {
                    int mt = ri >> 1, hf = ri & 1;
                    int t = m0 + mt * 16 + hf * 8 + g;
                    float mx = -3.0e38f;
                    #pragma unroll
                    for (int nt = 0; nt < 4; ++nt)
                        #pragma unroll
                        for (int j = 0; j < 2; ++j) {
                            int s = n0 + nt * 8 + qj * 2 + j;
                            float v = sc[mt * 4 + nt][hf * 2 + j];
                            if (s <= t) mx = fmaxf(mx, v);
                            else sc[mt * 4 + nt][hf * 2 + j] = -3.0e38f;
                        }
                    mx = fmaxf(mx, __shfl_xor_sync(0xffffffffu, mx, 1));
                    mx = fmaxf(mx, __shfl_xor_sync(0xffffffffu, mx, 2));
                    float s = 0.f;
                    #pragma unroll
                    for (int nt = 0; nt < 4; ++nt)
                        #pragma unroll
                        for (int j = 0; j < 2; ++j) {
                            float v = sc[mt * 4 + nt][hf * 2 + j];
                            float e = (v > -1.0e38f) ? __expf(v - mx) : 0.f;
                            sc[mt * 4 + nt][hf * 2 + j] = e;
                            s += e;
                        }
                    s += __shfl_xor_sync(0xffffffffu, s, 1);
                    s += __shfl_xor_sync(0xffffffffu, s, 2);
                    mloc[ri] = mx;
                    if (qj == 0) {
                        red[(wc * 2 + 0) * 128 + t] = mx;
                        red[(wc * 2 + 1) * 128 + t] = s;
                    }
                }
            } else if (qj == 0) {
                // dead tiles contribute max=-inf, sum=0
                #pragma unroll
                for (int ri = 0; ri < 4; ++ri) {
                    int mt = ri >> 1, hf = ri & 1;
                    int t = m0 + mt * 16 + hf * 8 + g;
                    red[(wc * 2 + 0) * 128 + t] = -3.0e38f;
                    red[(wc * 2 + 1) * 128 + t] = 0.f;
                }
            }
            __syncthreads();

            if (!dead) {
                #pragma unroll
                for (int ri = 0; ri < 4; ++ri) {
                    int mt = ri >> 1, hf = ri & 1;
                    int t = m0 + mt * 16 + hf * 8 + g;
                    float m = -3.0e38f;
                    #pragma unroll
                    for (int w4 = 0; w4 < 4; ++w4) m = fmaxf(m, red[(w4 * 2) * 128 + t]);
                    float sum = 0.f;
                    #pragma unroll
                    for (int w4 = 0; w4 < 4; ++w4)
                        sum += red[(w4 * 2 + 1) * 128 + t] * __expf(red[(w4 * 2) * 128 + t] - m);
                    fac[ri] = __expf(mloc[ri] - m) / sum;
                }
                // store P split (dead tiles never read by bounded G3)
                #pragma unroll
                for (int ri = 0; ri < 4; ++ri) {
                    int mt = ri >> 1, hf = ri & 1;
                    int t = m0 + mt * 16 + hf * 8 + g;
                    #pragma unroll
                    for (int nt = 0; nt < 4; ++nt) {
                        int s0 = n0 + nt * 8 + qj * 2;
                        st_split2(sm, O_PH, O_PL, (uint32_t)(t * S128 + s0 * 2),
                                  sc[mt * 4 + nt][hf * 2 + 0] * fac[ri],
                                  sc[mt * 4 + nt][hf * 2 + 1] * fac[ri]);
                    }
                }
            }
        }
        __syncthreads();

        // ---- G3: O = P V (M128 N32, causal-bounded K, trans-B x4 from V[s][d]) ----
        {
            const int m0 = wr * 32, n0 = wc * 8;
            float oc[2][4];
            #pragma unroll
            for (int f = 0; f < 2; ++f)
                #pragma unroll
                for (int r = 0; r < 4; ++r) oc[f][r] = 0.f;

            const uint32_t aPh = sb + O_PH + (m0 + (lane & 15)) * S128 + ((lane >> 4) * 8) * 2;
            const uint32_t aPl = sb + O_PL + (m0 + (lane & 15)) * S128 + ((lane >> 4) * 8) * 2;
            const uint32_t aVt = (uint32_t)lane * S32 + n0 * 2;   // 32 rows s per x4t
            const int kend = (wr + 1) * 32;                       // P[t][s]=0 for s>t
            for (int k32 = 0; k32 < kend; k32 += 32) {
                uint32_t vh[4], vl[4];
                ldsm4t(vh, sb + O_VH + aVt + k32 * S32);
                ldsm4t(vl, sb + O_VL + aVt + k32 * S32);
                #pragma unroll
                for (int kc = 0; kc < 2; ++kc) {
                    int k = k32 + kc * 16;
                    uint32_t ph[2][4], pl[2][4];
                    ldsm4(ph[0], aPh + k * 2);
                    ldsm4(ph[1], aPh + k * 2 + 16 * S128);
                    ldsm4(pl[0], aPl + k * 2);
                    ldsm4(pl[1], aPl + k * 2 + 16 * S128);
                    #pragma unroll
                    for (int mt = 0; mt < 2; ++mt) {
                        mma16816(oc[mt], ph[mt], vh + 2 * kc);
                        mma16816(oc[mt], ph[mt], vl + 2 * kc);
                        mma16816(oc[mt], pl[mt], vh + 2 * kc);
                    }
                }
            }
            #pragma unroll
            for (int mt = 0; mt < 2; ++mt)
                #pragma unroll
                for (int hf = 0; hf < 2; ++hf) {
                    int t = m0 + mt * 16 + hf * 8 + g;
                    int d0 = n0 + qj * 2;
                    st_split2(sm, O_OH, O_OL, (uint32_t)(t * S32 + d0 * 2),
                              oc[mt][hf * 2 + 0], oc[mt][hf * 2 + 1]);
                }
        }
        __syncthreads();

        // ---- G4: OUT += O Wp^T (M128 N128 K32, split 3-pass, reg-persistent) ----
        {
            const int m0 = wr * 32, n0 = wc * 32;
            const uint32_t aOh = sb + O_OH + (m0 + (lane & 15)) * S32 + ((lane >> 4) * 8) * 2;
            const uint32_t aOl = sb + O_OL + (m0 + (lane & 15)) * S32 + ((lane >> 4) * 8) * 2;
            const uint32_t aW4 = (uint32_t)(n0 + (lane >> 4) * 8 + (lane & 7)) * S32
                                 + (((lane >> 3) & 1) * 8) * 2;
            #pragma unroll
            for (int k = 0; k < 32; k += 16) {
                uint32_t oh[2][4], ol[2][4], wh[4][2], wl[4][2];
                ldsm4(oh[0], aOh + k * 2);
                ldsm4(oh[1], aOh + k * 2 + 16 * S32);
                ldsm4(ol[0], aOl + k * 2);
                ldsm4(ol[1], aOl + k * 2 + 16 * S32);
                ldsm4(&wh[0][0], sb + O_WPH + aW4 + k * 2);
                ldsm4(&wh[2][0], sb + O_WPH + aW4 + 16 * S32 + k * 2);
                ldsm4(&wl[0][0], sb + O_WPL + aW4 + k * 2);
                ldsm4(&wl[2][0], sb + O_WPL + aW4 + 16 * S32 + k * 2);
                #pragma unroll
                for (int mt = 0; mt < 2; ++mt)
                    #pragma unroll
                    for (int nt = 0; nt < 4; ++nt) {
                        mma16816(oacc[mt * 4 + nt], oh[mt], wh[nt]);
                        mma16816(oacc[mt * 4 + nt], oh[mt], wl[nt]);
                        mma16816(oacc[mt * 4 + nt], ol[mt], wh[nt]);
                    }
            }
        }
        __syncthreads();   // next head's staging overwrites W/Wp regions
    }

    // ---- final store: out = oacc + bp ----
    {
        const int m0 = wr * 32, n0 = wc * 32;
        #pragma unroll
        for (int mt = 0; mt < 2; ++mt)
            #pragma unroll
            for (int nt = 0; nt < 4; ++nt) {
                int c = n0 + nt * 8 + qj * 2;
                float2 bv = *reinterpret_cast<const float2*>(bp + c);
                #pragma unroll
                for (int hf = 0; hf < 2; ++hf) {
                    int t = m0 + mt * 16 + hf * 8 + g;
                    float2 v;
                    v.x = oacc[mt * 4 + nt][hf * 2 + 0] + bv.x;
                    v.y = oacc[mt * 4 + nt][hf * 2 + 1] + bv.y;
                    *reinterpret_cast<float2*>(out + ((size_t)b * 128 + t) * 128 + c) = v;
                }
            }
    }
}

extern "C" void kernel_launch(void* const* d_in, const int* in_sizes, int n_in,
                              void* d_out, int out_size)
{
    (void)in_sizes; (void)n_in; (void)out_size;
    const float* x  = (const float*)d_in[0];
    const float* Wq = (const float*)d_in[1];
    const float* Wk = (const float*)d_in[2];
    const float* Wv = (const float*)d_in[3];
    const float* Wp = (const float*)d_in[4];
    const float* bp = (const float*)d_in[5];
    float* out = (float*)d_out;

    cudaFuncSetAttribute(mha_mma_kernel,
                         cudaFuncAttributeMaxDynamicSharedMemorySize, SMEM_BYTES);
    mha_mma_kernel<<<NB, 512, SMEM_BYTES>>>(x, Wq, Wk, Wv, Wp, bp, out);
}